// round 1
// baseline (speedup 1.0000x reference)
#include <cuda_runtime.h>
#include <math.h>

// Problem constants (fixed by dataset)
#define N_MAX 100000
#define E_MAX 1600000

// ---------------- scratch (device globals; allocation-free) ----------------
__device__ float g_dinv[N_MAX];                       // deg, then rsqrt(deg) in place
__device__ float g_norm[E_MAX];                       // per-edge dinv[s]*dinv[d]
__device__ __align__(16) float g_h1  [N_MAX * 32];    // x @ W1
__device__ __align__(16) float g_acc1[N_MAX * 32];    // aggregated layer-1
__device__ __align__(16) float g_h2  [N_MAX * 16];    // relu(acc1+b1) @ W2
__device__ __align__(16) float g_acc2[N_MAX * 16];    // aggregated layer-2

// ---------------- kernels ----------------

// deg init: self-loop contributes 1
__global__ void k_deg_init(int n) {
    int i = blockIdx.x * blockDim.x + threadIdx.x;
    if (i < n) g_dinv[i] = 1.0f;
}

// deg scatter over dst
__global__ void k_deg_edges(const int* __restrict__ dst, int e) {
    int i = blockIdx.x * blockDim.x + threadIdx.x;
    if (i < e) atomicAdd(&g_dinv[__ldg(dst + i)], 1.0f);
}

// dinv = rsqrt(deg), in place
__global__ void k_dinv(int n) {
    int i = blockIdx.x * blockDim.x + threadIdx.x;
    if (i < n) g_dinv[i] = rsqrtf(g_dinv[i]);
}

// per-edge normalization coefficient
__global__ void k_norm(const int* __restrict__ src, const int* __restrict__ dst, int e) {
    int i = blockIdx.x * blockDim.x + threadIdx.x;
    if (i < e) g_norm[i] = g_dinv[__ldg(src + i)] * g_dinv[__ldg(dst + i)];
}

// h1 = x @ W1 ; acc1 = h1 * dinv^2 (self-loop message preloaded)
// block: 256 threads = 32 nodes x 8 channel-groups (4 ch each)
__global__ void k_mm1(const float* __restrict__ x, const float* __restrict__ W1, int n) {
    __shared__ float sW[8 * 32];
    int tid = threadIdx.x;
    if (tid < 256) sW[tid] = __ldg(W1 + tid);
    __syncthreads();
    int node = blockIdx.x * 32 + (tid >> 3);
    int g = tid & 7;
    if (node >= n) return;

    const float4* xr = reinterpret_cast<const float4*>(x + node * 8);
    float4 x0 = __ldg(xr), x1 = __ldg(xr + 1);
    float xv[8] = {x0.x, x0.y, x0.z, x0.w, x1.x, x1.y, x1.z, x1.w};

    float o[4];
#pragma unroll
    for (int j = 0; j < 4; j++) {
        int c = g * 4 + j;
        float s = 0.f;
#pragma unroll
        for (int k = 0; k < 8; k++) s = fmaf(xv[k], sW[k * 32 + c], s);
        o[j] = s;
    }
    float di = g_dinv[node];
    float di2 = di * di;
    float4 hv = make_float4(o[0], o[1], o[2], o[3]);
    float4 av = make_float4(o[0] * di2, o[1] * di2, o[2] * di2, o[3] * di2);
    *reinterpret_cast<float4*>(g_h1 + node * 32 + g * 4) = hv;
    *reinterpret_cast<float4*>(g_acc1 + node * 32 + g * 4) = av;
}

// layer-1 edge scatter: 8 lanes per edge, float4 red per lane
__global__ void k_edge1(const int* __restrict__ src, const int* __restrict__ dst, int e) {
    int t = blockIdx.x * blockDim.x + threadIdx.x;
    int ed = t >> 3;
    if (ed >= e) return;
    int g = t & 7;
    int s = __ldg(src + ed);
    int d = __ldg(dst + ed);
    float nm = g_norm[ed];
    float4 h = *reinterpret_cast<const float4*>(g_h1 + s * 32 + g * 4);
    float4 m = make_float4(h.x * nm, h.y * nm, h.z * nm, h.w * nm);
    atomicAdd(reinterpret_cast<float4*>(g_acc1 + d * 32 + g * 4), m);
}

// v = relu(acc1 + b1); h2 = v @ W2 ; acc2 = h2 * dinv^2
// block: 256 threads = 64 nodes x 4 channel-groups (4 ch each)
__global__ void k_mm2(const float* __restrict__ b1, const float* __restrict__ W2, int n) {
    __shared__ float sW[32 * 16];
    __shared__ float sb[32];
    int tid = threadIdx.x;
    sW[tid] = __ldg(W2 + tid);
    sW[tid + 256] = __ldg(W2 + tid + 256);
    if (tid < 32) sb[tid] = __ldg(b1 + tid);
    __syncthreads();

    int node = blockIdx.x * 64 + (tid >> 2);
    int g = tid & 3;
    if (node >= n) return;

    float v[32];
    const float4* ar = reinterpret_cast<const float4*>(g_acc1 + node * 32);
#pragma unroll
    for (int q = 0; q < 8; q++) {
        float4 a = ar[q];
        v[q * 4 + 0] = fmaxf(a.x + sb[q * 4 + 0], 0.f);
        v[q * 4 + 1] = fmaxf(a.y + sb[q * 4 + 1], 0.f);
        v[q * 4 + 2] = fmaxf(a.z + sb[q * 4 + 2], 0.f);
        v[q * 4 + 3] = fmaxf(a.w + sb[q * 4 + 3], 0.f);
    }

    float o[4];
#pragma unroll
    for (int j = 0; j < 4; j++) {
        int c = g * 4 + j;
        float s = 0.f;
#pragma unroll
        for (int k = 0; k < 32; k++) s = fmaf(v[k], sW[k * 16 + c], s);
        o[j] = s;
    }
    float di = g_dinv[node];
    float di2 = di * di;
    *reinterpret_cast<float4*>(g_h2 + node * 16 + g * 4) =
        make_float4(o[0], o[1], o[2], o[3]);
    *reinterpret_cast<float4*>(g_acc2 + node * 16 + g * 4) =
        make_float4(o[0] * di2, o[1] * di2, o[2] * di2, o[3] * di2);
}

// layer-2 edge scatter: 4 lanes per edge, float4 red per lane
__global__ void k_edge2(const int* __restrict__ src, const int* __restrict__ dst, int e) {
    int t = blockIdx.x * blockDim.x + threadIdx.x;
    int ed = t >> 2;
    if (ed >= e) return;
    int g = t & 3;
    int s = __ldg(src + ed);
    int d = __ldg(dst + ed);
    float nm = g_norm[ed];
    float4 h = *reinterpret_cast<const float4*>(g_h2 + s * 16 + g * 4);
    float4 m = make_float4(h.x * nm, h.y * nm, h.z * nm, h.w * nm);
    atomicAdd(reinterpret_cast<float4*>(g_acc2 + d * 16 + g * 4), m);
}

// out = sigmoid(relu(acc2 + b2) @ Wfc + bfc)
__global__ void k_fin(const float* __restrict__ b2, const float* __restrict__ Wfc,
                      const float* __restrict__ bfc, float* __restrict__ out, int n) {
    int i = blockIdx.x * blockDim.x + threadIdx.x;
    if (i >= n) return;
    const float4* ar = reinterpret_cast<const float4*>(g_acc2 + i * 16);
    float s = __ldg(bfc);
#pragma unroll
    for (int q = 0; q < 4; q++) {
        float4 a = ar[q];
        s = fmaf(fmaxf(a.x + __ldg(b2 + q * 4 + 0), 0.f), __ldg(Wfc + q * 4 + 0), s);
        s = fmaf(fmaxf(a.y + __ldg(b2 + q * 4 + 1), 0.f), __ldg(Wfc + q * 4 + 1), s);
        s = fmaf(fmaxf(a.z + __ldg(b2 + q * 4 + 2), 0.f), __ldg(Wfc + q * 4 + 2), s);
        s = fmaf(fmaxf(a.w + __ldg(b2 + q * 4 + 3), 0.f), __ldg(Wfc + q * 4 + 3), s);
    }
    out[i] = 1.0f / (1.0f + expf(-s));
}

// ---------------- launch ----------------
extern "C" void kernel_launch(void* const* d_in, const int* in_sizes, int n_in,
                              void* d_out, int out_size) {
    const float* x   = (const float*)d_in[0];
    const int*   ei  = (const int*)d_in[1];
    const float* W1  = (const float*)d_in[2];
    const float* b1  = (const float*)d_in[3];
    const float* W2  = (const float*)d_in[4];
    const float* b2  = (const float*)d_in[5];
    const float* Wfc = (const float*)d_in[6];
    const float* bfc = (const float*)d_in[7];
    float* out = (float*)d_out;

    int n = in_sizes[0] / 8;        // 100000
    int e = in_sizes[1] / 2;        // 1600000
    const int* src = ei;
    const int* dst = ei + e;

    const int B = 256;
    int gn  = (n + B - 1) / B;
    int ge  = (e + B - 1) / B;

    k_deg_init<<<gn, B>>>(n);
    k_deg_edges<<<ge, B>>>(dst, e);
    k_dinv<<<gn, B>>>(n);
    k_norm<<<ge, B>>>(src, dst, e);

    k_mm1<<<(n + 31) / 32, B>>>(x, W1, n);
    {
        long long t = (long long)e * 8;
        k_edge1<<<(int)((t + B - 1) / B), B>>>(src, dst, e);
    }
    k_mm2<<<(n + 63) / 64, B>>>(b1, W2, n);
    {
        long long t = (long long)e * 4;
        k_edge2<<<(int)((t + B - 1) / B), B>>>(src, dst, e);
    }
    k_fin<<<gn, B>>>(b2, Wfc, bfc, out, n);
}